// round 6
// baseline (speedup 1.0000x reference)
#include <cuda_runtime.h>
#include <cuda_bf16.h>
#include <cuda_fp16.h>
#include <stdint.h>

// VQ-VAE quantization. R6: warp-level HMMA (mma.sync bf16, plain sm_103
// feature -- tcgen05 is rejected by the harness's non-'a' PTX target) computes
// approximate scores s=en-2*dot; positions whose top-2 gap <= 1e-3 are
// re-arbitrated with the bit-validated exact fp32 chain (R2-R4, rel_err==0.0).

#define BATCH 64
#define DIM   256
#define KCB   512
#define HWSZ  1024
#define TM    128
#define SEC   ((size_t)BATCH * DIM * HWSZ)
#define APITCH 528               // smem row pitch: 264 bf16 (conflict-free ldmatrix)
#define FLAG_M 1e-3f
#define CAND_M 1.3e-3f

__device__ float d_enorm[KCB];
__device__ float d_zn[BATCH * HWSZ];
__device__ __nv_bfloat16 d_ebf[KCB * DIM];
__device__ __nv_bfloat16 d_xbf[(size_t)BATCH * HWSZ * DIM];
__device__ __half d_scr[(size_t)BATCH * HWSZ * KCB];     // 64 MB score scratch

__device__ __forceinline__ uint32_t smem_u32(const void* p) {
    uint32_t a;
    asm("{ .reg .u64 t; cvta.to.shared.u64 t, %1; cvt.u32.u64 %0, t; }"
        : "=r"(a) : "l"(p));
    return a;
}
__device__ __forceinline__ void ldsm4(uint32_t r[4], uint32_t addr) {
    asm volatile("ldmatrix.sync.aligned.m8n8.x4.shared.b16 {%0,%1,%2,%3}, [%4];"
                 : "=r"(r[0]), "=r"(r[1]), "=r"(r[2]), "=r"(r[3]) : "r"(addr));
}
__device__ __forceinline__ void mma16816(float c[4], const uint32_t a[4],
                                         uint32_t b0, uint32_t b1) {
    asm volatile("mma.sync.aligned.m16n8k16.row.col.f32.bf16.bf16.f32 "
                 "{%0,%1,%2,%3}, {%4,%5,%6,%7}, {%8,%9}, {%0,%1,%2,%3};"
                 : "+f"(c[0]), "+f"(c[1]), "+f"(c[2]), "+f"(c[3])
                 : "r"(a[0]), "r"(a[1]), "r"(a[2]), "r"(a[3]), "r"(b0), "r"(b1));
}

// ---------------- prep ----------------
__global__ void prep_e(const float* __restrict__ emb) {
    int k = blockIdx.x * blockDim.x + threadIdx.x;
    if (k >= KCB) return;
    const float* e = emb + (size_t)k * DIM;
    uint32_t* eb = ((uint32_t*)d_ebf) + (size_t)k * (DIM / 2);
    float acc = 0.f;
    for (int j = 0; j < DIM / 2; ++j) {
        float v0 = e[2 * j], v1 = e[2 * j + 1];
        acc = __fadd_rn(acc, __fmul_rn(v0, v0));   // validated sequential chain
        acc = __fadd_rn(acc, __fmul_rn(v1, v1));
        eb[j] = (uint32_t)__bfloat16_as_ushort(__float2bfloat16(v0)) |
                ((uint32_t)__bfloat16_as_ushort(__float2bfloat16(v1)) << 16);
    }
    d_enorm[k] = acc;
}

__global__ __launch_bounds__(256) void prep_x(const float* __restrict__ x) {
    __shared__ float st[32][257];
    const int t  = threadIdx.x;
    const int p0 = blockIdx.x * 256;
    const int b  = p0 >> 10;
    const int pb = p0 & 1023;
    float acc = 0.f;
    for (int ch = 0; ch < 8; ++ch) {
        #pragma unroll 4
        for (int i = 0; i < 32; ++i) {
            int d = ch * 32 + i;
            st[i][t] = x[(size_t)b * DIM * HWSZ + (size_t)d * HWSZ + pb + t];
        }
        __syncthreads();
        uint32_t pk[16];
        #pragma unroll
        for (int j = 0; j < 16; ++j) {
            float v0 = st[2 * j][t], v1 = st[2 * j + 1][t];
            acc = __fadd_rn(acc, __fmul_rn(v0, v0));   // validated chain order
            acc = __fadd_rn(acc, __fmul_rn(v1, v1));
            pk[j] = (uint32_t)__bfloat16_as_ushort(__float2bfloat16(v0)) |
                    ((uint32_t)__bfloat16_as_ushort(__float2bfloat16(v1)) << 16);
        }
        uint4* dst = (uint4*)(d_xbf + (size_t)(p0 + t) * DIM + ch * 32);
        #pragma unroll
        for (int q = 0; q < 4; ++q) dst[q] = ((uint4*)pk)[q];
        __syncthreads();
    }
    d_zn[p0 + t] = acc;
}

// ---------------- main ----------------
__global__ __launch_bounds__(256, 1) void vq_main(const float* __restrict__ x,
                                                  const float* __restrict__ emb,
                                                  float* __restrict__ out) {
    extern __shared__ char dsm[];
    __shared__ float en_s[KCB];
    __shared__ float amin_s[TM], amin2_s[TM];
    __shared__ int kmin_s[TM], idx_s[TM];

    const int t   = threadIdx.x;
    const int wid = t >> 5;
    const int l   = t & 31;
    const int p0  = blockIdx.x * TM;
    const int b   = p0 >> 10;
    const int pb0 = p0 & 1023;

    char* Ap = dsm;
    char* Bp = dsm + 128 * APITCH;
    const uint32_t Aaddr = smem_u32(Ap);
    const uint32_t Baddr = smem_u32(Bp);

    en_s[t]       = d_enorm[t];
    en_s[t + 256] = d_enorm[t + 256];

    // stage A tile: 128 pos x 256 bf16, padded rows
    {
        const uint4* src = (const uint4*)d_xbf;
        #pragma unroll
        for (int it = 0; it < 16; ++it) {
            int i = t + it * 256, row = i >> 5, seg = i & 31;
            *(uint4*)(Ap + row * APITCH + seg * 16) = src[(size_t)(p0 + row) * 32 + seg];
        }
    }
    __syncthreads();

    // A fragments, register-resident for all chunks: 16 k-steps x 4 regs
    const int m0 = wid * 16;
    uint32_t af[16][4];
    {
        uint32_t base = Aaddr + (uint32_t)(m0 + (l & 15)) * APITCH + (uint32_t)(l >> 4) * 16;
        #pragma unroll
        for (int ks = 0; ks < 16; ++ks) ldsm4(af[ks], base + ks * 32);
    }

    float min1a = 1e30f, min2a = 1e30f, min1b = 1e30f, min2b = 1e30f;
    int kma = 0, kmb = 0;
    const int mg0 = p0 + m0 + (l >> 2);   // global position (slot A)
    const int mg1 = mg0 + 8;              // slot B

    for (int nc = 0; nc < 4; ++nc) {
        __syncthreads();
        {
            const uint4* src = (const uint4*)d_ebf;
            #pragma unroll
            for (int it = 0; it < 16; ++it) {
                int i = t + it * 256, row = i >> 5, seg = i & 31;
                *(uint4*)(Bp + row * APITCH + seg * 16) =
                    src[(size_t)(nc * 128 + row) * 32 + seg];
            }
        }
        __syncthreads();

        const uint32_t bbase = Baddr + (uint32_t)(l & 7) * APITCH + (uint32_t)(l >> 3) * 16;
        for (int nt = 0; nt < 16; ++nt) {
            float c[4] = {0.f, 0.f, 0.f, 0.f};
            const uint32_t baddr = bbase + (uint32_t)nt * 8 * APITCH;
            #pragma unroll
            for (int ksp = 0; ksp < 8; ++ksp) {
                uint32_t br[4];
                ldsm4(br, baddr + ksp * 64);
                mma16816(c, af[2 * ksp],     br[0], br[1]);
                mma16816(c, af[2 * ksp + 1], br[2], br[3]);
            }
            const int kb = nc * 128 + nt * 8 + ((l & 3) << 1);
            const float en0 = en_s[kb], en1 = en_s[kb + 1];
            float s0 = fmaf(-2.f, c[0], en0), s1 = fmaf(-2.f, c[1], en1);
            float s2 = fmaf(-2.f, c[2], en0), s3 = fmaf(-2.f, c[3], en1);
            *(__half2*)(d_scr + (size_t)mg0 * KCB + kb) = __floats2half2_rn(s0, s1);
            *(__half2*)(d_scr + (size_t)mg1 * KCB + kb) = __floats2half2_rn(s2, s3);
            if (s0 < min1a) { min2a = min1a; min1a = s0; kma = kb; }
            else if (s0 < min2a) min2a = s0;
            if (s1 < min1a) { min2a = min1a; min1a = s1; kma = kb + 1; }
            else if (s1 < min2a) min2a = s1;
            if (s2 < min1b) { min2b = min1b; min1b = s2; kmb = kb; }
            else if (s2 < min2b) min2b = s2;
            if (s3 < min1b) { min2b = min1b; min1b = s3; kmb = kb + 1; }
            else if (s3 < min2b) min2b = s3;
        }
    }

    // merge (min1, min2, argmin) across the 4 lanes of each quad
    #pragma unroll
    for (int msk = 1; msk <= 2; msk <<= 1) {
        float o1 = __shfl_xor_sync(0xFFFFFFFFu, min1a, msk);
        float o2 = __shfl_xor_sync(0xFFFFFFFFu, min2a, msk);
        int   ok = __shfl_xor_sync(0xFFFFFFFFu, kma,  msk);
        float hi = fmaxf(min1a, o1);
        if (o1 < min1a) { min1a = o1; kma = ok; }
        min2a = fminf(fminf(min2a, o2), hi);
        o1 = __shfl_xor_sync(0xFFFFFFFFu, min1b, msk);
        o2 = __shfl_xor_sync(0xFFFFFFFFu, min2b, msk);
        ok = __shfl_xor_sync(0xFFFFFFFFu, kmb,  msk);
        hi = fmaxf(min1b, o1);
        if (o1 < min1b) { min1b = o1; kmb = ok; }
        min2b = fminf(fminf(min2b, o2), hi);
    }
    if ((l & 3) == 0) {
        const int pa = m0 + (l >> 2);
        amin_s[pa] = min1a;  amin2_s[pa] = min2a;  kmin_s[pa] = kma;
        amin_s[pa + 8] = min1b;  amin2_s[pa + 8] = min2b;  kmin_s[pa + 8] = kmb;
    }
    __syncthreads();

    // exact arbitration of near-ties (validated fp32 chain + rn + tiebreak)
    if (t < TM) {
        int kfin = kmin_s[t];
        if (amin2_s[t] - amin_s[t] <= FLAG_M) {
            const int gp = p0 + t;
            const int pbi = pb0 + t;
            const float znv = d_zn[gp];
            const float lim = amin_s[t] + CAND_M;
            const __half2* sc = (const __half2*)(d_scr + (size_t)gp * KCB);
            unsigned long long best = ~0ull;
            for (int k2 = 0; k2 < KCB / 2; ++k2) {
                float2 sv = __half22float2(sc[k2]);
                #pragma unroll
                for (int e = 0; e < 2; ++e) {
                    float s = e ? sv.y : sv.x;
                    if (s <= lim) {
                        const int k = 2 * k2 + e;
                        const float* er = emb + (size_t)k * DIM;
                        const float* xc = x + (size_t)b * DIM * HWSZ + pbi;
                        float acc = 0.f;
                        #pragma unroll 8
                        for (int d = 0; d < DIM; ++d)
                            acc = fmaf(er[d], xc[(size_t)d * HWSZ], acc);
                        float dist = __fadd_rn(__fadd_rn(znv, en_s[k]),
                                               __fmul_rn(-2.f, acc));
                        unsigned u = __float_as_uint(dist);
                        u = (u & 0x80000000u) ? ~u : (u | 0x80000000u);
                        unsigned long long key = ((unsigned long long)u << 32) | (unsigned)k;
                        if (key < best) best = key;
                    }
                }
            }
            kfin = (int)(best & 0xFFFFFFFFull);
        }
        idx_s[t] = kfin;
    }
    __syncthreads();

    // outputs (validated rounding), coalesced 512B rows
    {
        const int pos = t & 127, dh = t >> 7;
        const int kq = idx_s[pos];
        const int pbi = pb0 + pos;
        const float* er = emb + (size_t)kq * DIM;
        const size_t gb = (size_t)b * DIM * HWSZ + pbi;
        #pragma unroll 4
        for (int d = dh * 128; d < dh * 128 + 128; ++d) {
            float v = __ldg(&er[d]);
            size_t off = gb + (size_t)d * HWSZ;
            float z = __ldg(&x[off]);
            out[off]           = __fadd_rn(z, __fadd_rn(v, -z));
            out[off + SEC]     = z;
            out[off + 2 * SEC] = v;
        }
    }
}

extern "C" void kernel_launch(void* const* d_in, const int* in_sizes, int n_in,
                              void* d_out, int out_size) {
    const float* x   = (const float*)d_in[0];
    const float* emb = (const float*)d_in[1];
    float* out = (float*)d_out;
    (void)in_sizes; (void)n_in; (void)out_size;

    static int smem_set = 0;
    const int dyn = 2 * 128 * APITCH;   // A + B tiles, 135168 B
    if (!smem_set) {
        cudaFuncSetAttribute(vq_main, cudaFuncAttributeMaxDynamicSharedMemorySize, dyn);
        smem_set = 1;
    }

    prep_e<<<2, 256>>>(emb);
    prep_x<<<BATCH * HWSZ / 256, 256>>>(x);
    vq_main<<<BATCH * HWSZ / TM, 256, dyn>>>(x, emb, out);
}

// round 7
// speedup vs baseline: 2.7756x; 2.7756x over previous
#include <cuda_runtime.h>
#include <cuda_bf16.h>
#include <cuda_fp16.h>
#include <stdint.h>

// VQ-VAE quantization. R7: HMMA bf16 approx scores (layout validated R6,
// rel_err==0.0) + coalesced fp16 score scratch + warp-cooperative exact
// arbitration of near-ties (validated sequential-chain fp32 arithmetic).

#define BATCH 64
#define DIM   256
#define KCB   512
#define HWSZ  1024
#define NPOS  65536
#define TM    128
#define SEC   ((size_t)BATCH * DIM * HWSZ)
#define APITCH 528               // A/B smem row pitch (bytes)
#define SPITCH 272               // score smem row pitch (bytes), 128 halves + pad
#define FLAG_M 1e-3f             // validated R6
#define CAND_M 1.6e-3f           // >= validated 1.3e-3 + fp16 slack

__device__ float d_enorm[KCB];
__device__ float d_zn[NPOS];
__device__ __nv_bfloat16 d_ebf[KCB * DIM];
__device__ __nv_bfloat16 d_xbf[(size_t)NPOS * DIM];
__device__ __half d_scr[(size_t)NPOS * KCB];     // 64 MB, coalesced [p][k]
__device__ int d_idx[NPOS];
__device__ int d_flag[NPOS];

__device__ __forceinline__ uint32_t smem_u32(const void* p) {
    uint32_t a;
    asm("{ .reg .u64 t; cvta.to.shared.u64 t, %1; cvt.u32.u64 %0, t; }"
        : "=r"(a) : "l"(p));
    return a;
}
__device__ __forceinline__ void ldsm4(uint32_t r[4], uint32_t addr) {
    asm volatile("ldmatrix.sync.aligned.m8n8.x4.shared.b16 {%0,%1,%2,%3}, [%4];"
                 : "=r"(r[0]), "=r"(r[1]), "=r"(r[2]), "=r"(r[3]) : "r"(addr));
}
__device__ __forceinline__ void mma16816(float c[4], const uint32_t a[4],
                                         uint32_t b0, uint32_t b1) {
    asm volatile("mma.sync.aligned.m16n8k16.row.col.f32.bf16.bf16.f32 "
                 "{%0,%1,%2,%3}, {%4,%5,%6,%7}, {%8,%9}, {%0,%1,%2,%3};"
                 : "+f"(c[0]), "+f"(c[1]), "+f"(c[2]), "+f"(c[3])
                 : "r"(a[0]), "r"(a[1]), "r"(a[2]), "r"(a[3]), "r"(b0), "r"(b1));
}

// ---------------- fused prep: blocks 0..255 transpose x, 256..271 do emb ----
__global__ __launch_bounds__(256) void prep(const float* __restrict__ x,
                                            const float* __restrict__ emb) {
    if (blockIdx.x >= 256) {
        // codebook: bf16 copy + sequential-chain norm (validated order)
        const int t = threadIdx.x;
        if (t < 32) {
            const int k = (blockIdx.x - 256) * 32 + t;
            const float4* e4 = (const float4*)(emb + (size_t)k * DIM);
            uint32_t* eb = ((uint32_t*)d_ebf) + (size_t)k * (DIM / 2);
            float acc = 0.f;
            #pragma unroll 4
            for (int j = 0; j < DIM / 4; ++j) {
                float4 v = e4[j];
                acc = __fadd_rn(acc, __fmul_rn(v.x, v.x));
                acc = __fadd_rn(acc, __fmul_rn(v.y, v.y));
                acc = __fadd_rn(acc, __fmul_rn(v.z, v.z));
                acc = __fadd_rn(acc, __fmul_rn(v.w, v.w));
                eb[2 * j] = (uint32_t)__bfloat16_as_ushort(__float2bfloat16(v.x)) |
                            ((uint32_t)__bfloat16_as_ushort(__float2bfloat16(v.y)) << 16);
                eb[2 * j + 1] = (uint32_t)__bfloat16_as_ushort(__float2bfloat16(v.z)) |
                                ((uint32_t)__bfloat16_as_ushort(__float2bfloat16(v.w)) << 16);
            }
            d_enorm[k] = acc;
        }
        return;
    }
    __shared__ float st[32][257];
    const int t  = threadIdx.x;
    const int p0 = blockIdx.x * 256;
    const int b  = p0 >> 10;
    const int pb = p0 & 1023;
    float acc = 0.f;
    for (int ch = 0; ch < 8; ++ch) {
        #pragma unroll 4
        for (int i = 0; i < 32; ++i) {
            int d = ch * 32 + i;
            st[i][t] = x[(size_t)b * DIM * HWSZ + (size_t)d * HWSZ + pb + t];
        }
        __syncthreads();
        uint32_t pk[16];
        #pragma unroll
        for (int j = 0; j < 16; ++j) {
            float v0 = st[2 * j][t], v1 = st[2 * j + 1][t];
            acc = __fadd_rn(acc, __fmul_rn(v0, v0));   // validated chain order
            acc = __fadd_rn(acc, __fmul_rn(v1, v1));
            pk[j] = (uint32_t)__bfloat16_as_ushort(__float2bfloat16(v0)) |
                    ((uint32_t)__bfloat16_as_ushort(__float2bfloat16(v1)) << 16);
        }
        uint4* dst = (uint4*)(d_xbf + (size_t)(p0 + t) * DIM + ch * 32);
        #pragma unroll
        for (int q = 0; q < 4; ++q) dst[q] = ((uint4*)pk)[q];
        __syncthreads();
    }
    d_zn[p0 + t] = acc;
}

// ---------------- main: HMMA scores -> scratch + idx/flag ----------------
__global__ __launch_bounds__(256, 1) void vq_main() {
    extern __shared__ char dsm[];
    __shared__ float en_s[KCB];
    __shared__ float amin_s[TM], amin2_s[TM];
    __shared__ int kmin_s[TM];

    const int t   = threadIdx.x;
    const int wid = t >> 5;
    const int l   = t & 31;
    const int p0  = blockIdx.x * TM;

    char* Ap = dsm;
    char* Bp = dsm + 128 * APITCH;
    char* Sp = dsm + 2 * 128 * APITCH;
    const uint32_t Aaddr = smem_u32(Ap);
    const uint32_t Baddr = smem_u32(Bp);

    en_s[t]       = d_enorm[t];
    en_s[t + 256] = d_enorm[t + 256];

    {   // stage A tile (128 pos x 256 bf16)
        const uint4* src = (const uint4*)d_xbf;
        #pragma unroll
        for (int it = 0; it < 16; ++it) {
            int i = t + it * 256, row = i >> 5, seg = i & 31;
            *(uint4*)(Ap + row * APITCH + seg * 16) = src[(size_t)(p0 + row) * 32 + seg];
        }
    }
    __syncthreads();

    const int m0 = wid * 16;
    uint32_t af[16][4];                     // A frags, resident for all chunks
    {
        uint32_t base = Aaddr + (uint32_t)(m0 + (l & 15)) * APITCH + (uint32_t)(l >> 4) * 16;
        #pragma unroll
        for (int ks = 0; ks < 16; ++ks) ldsm4(af[ks], base + ks * 32);
    }

    float min1a = 1e30f, min2a = 1e30f, min1b = 1e30f, min2b = 1e30f;
    int kma = 0, kmb = 0;
    const int row0 = m0 + (l >> 2);

    for (int nc = 0; nc < 4; ++nc) {
        __syncthreads();
        {
            const uint4* src = (const uint4*)d_ebf;
            #pragma unroll
            for (int it = 0; it < 16; ++it) {
                int i = t + it * 256, row = i >> 5, seg = i & 31;
                *(uint4*)(Bp + row * APITCH + seg * 16) =
                    src[(size_t)(nc * 128 + row) * 32 + seg];
            }
        }
        __syncthreads();

        const uint32_t bbase = Baddr + (uint32_t)(l & 7) * APITCH + (uint32_t)(l >> 3) * 16;
        for (int nt = 0; nt < 16; ++nt) {
            float c[4] = {0.f, 0.f, 0.f, 0.f};
            const uint32_t baddr = bbase + (uint32_t)nt * 8 * APITCH;
            #pragma unroll
            for (int ksp = 0; ksp < 8; ++ksp) {
                uint32_t br[4];
                ldsm4(br, baddr + ksp * 64);
                mma16816(c, af[2 * ksp],     br[0], br[1]);
                mma16816(c, af[2 * ksp + 1], br[2], br[3]);
            }
            const int col = nt * 8 + ((l & 3) << 1);     // k within chunk
            const int kb  = nc * 128 + col;
            const float en0 = en_s[kb], en1 = en_s[kb + 1];
            float s0 = fmaf(-2.f, c[0], en0), s1 = fmaf(-2.f, c[1], en1);
            float s2 = fmaf(-2.f, c[2], en0), s3 = fmaf(-2.f, c[3], en1);
            *(__half2*)(Sp + row0 * SPITCH + col * 2)       = __floats2half2_rn(s0, s1);
            *(__half2*)(Sp + (row0 + 8) * SPITCH + col * 2) = __floats2half2_rn(s2, s3);
            if (s0 < min1a) { min2a = min1a; min1a = s0; kma = kb; }
            else if (s0 < min2a) min2a = s0;
            if (s1 < min1a) { min2a = min1a; min1a = s1; kma = kb + 1; }
            else if (s1 < min2a) min2a = s1;
            if (s2 < min1b) { min2b = min1b; min1b = s2; kmb = kb; }
            else if (s2 < min2b) min2b = s2;
            if (s3 < min1b) { min2b = min1b; min1b = s3; kmb = kb + 1; }
            else if (s3 < min2b) min2b = s3;
        }
        __syncthreads();
        // coalesced copy: score tile -> d_scr[p][nc*128 ..]
        #pragma unroll
        for (int it = 0; it < 8; ++it) {
            int i = t + it * 256, row = i >> 4, seg = i & 15;
            uint4 v = *(uint4*)(Sp + row * SPITCH + seg * 16);
            *(uint4*)((char*)d_scr + ((size_t)(p0 + row) * KCB + nc * 128) * 2 + seg * 16) = v;
        }
    }

    // merge (min1, min2, argmin) across each quad
    #pragma unroll
    for (int msk = 1; msk <= 2; msk <<= 1) {
        float o1 = __shfl_xor_sync(0xFFFFFFFFu, min1a, msk);
        float o2 = __shfl_xor_sync(0xFFFFFFFFu, min2a, msk);
        int   ok = __shfl_xor_sync(0xFFFFFFFFu, kma,  msk);
        float hi = fmaxf(min1a, o1);
        if (o1 < min1a) { min1a = o1; kma = ok; }
        min2a = fminf(fminf(min2a, o2), hi);
        o1 = __shfl_xor_sync(0xFFFFFFFFu, min1b, msk);
        o2 = __shfl_xor_sync(0xFFFFFFFFu, min2b, msk);
        ok = __shfl_xor_sync(0xFFFFFFFFu, kmb,  msk);
        hi = fmaxf(min1b, o1);
        if (o1 < min1b) { min1b = o1; kmb = ok; }
        min2b = fminf(fminf(min2b, o2), hi);
    }
    if ((l & 3) == 0) {
        const int pa = m0 + (l >> 2);
        amin_s[pa] = min1a;  amin2_s[pa] = min2a;  kmin_s[pa] = kma;
        amin_s[pa + 8] = min1b;  amin2_s[pa + 8] = min2b;  kmin_s[pa + 8] = kmb;
    }
    __syncthreads();
    if (t < TM) {
        d_idx[p0 + t]  = kmin_s[t];
        d_flag[p0 + t] = (amin2_s[t] - amin_s[t] <= FLAG_M) ? 1 : 0;
    }
}

// ---------------- fixup: warp-cooperative exact arbitration ----------------
__global__ __launch_bounds__(256) void fixup(const float* __restrict__ x,
                                             const float* __restrict__ emb) {
    const int wid = threadIdx.x >> 5;
    const int l   = threadIdx.x & 31;
    const int p   = blockIdx.x * 8 + wid;
    if (!d_flag[p]) return;                         // warp-uniform

    const int b  = p >> 10;
    const int pb = p & 1023;

    // coalesced 1 KB score-row read: lane owns k = l*16 .. l*16+15
    const uint4* rowq = (const uint4*)(d_scr + (size_t)p * KCB);
    __half2 hh[8];
    *(uint4*)&hh[0] = rowq[l * 2];
    *(uint4*)&hh[4] = rowq[l * 2 + 1];
    float s[16];
    #pragma unroll
    for (int j = 0; j < 8; ++j) {
        float2 f = __half22float2(hh[j]);
        s[2 * j] = f.x;  s[2 * j + 1] = f.y;
    }
    float smin = s[0];
    #pragma unroll
    for (int j = 1; j < 16; ++j) smin = fminf(smin, s[j]);
    #pragma unroll
    for (int m = 16; m >= 1; m >>= 1)
        smin = fminf(smin, __shfl_xor_sync(0xFFFFFFFFu, smin, m));
    const float lim = smin + CAND_M;

    // lane's d-slice of x (8 floats)
    const float* xc = x + (size_t)b * DIM * HWSZ + pb;
    float xv[8];
    #pragma unroll
    for (int j = 0; j < 8; ++j)
        xv[j] = __ldg(&xc[(size_t)(l * 8 + j) * HWSZ]);
    const float znv = d_zn[p];

    unsigned long long best = ~0ull;
    for (int c = 0; c < 16; ++c) {
        unsigned mask = __ballot_sync(0xFFFFFFFFu, s[c] <= lim);
        while (mask) {
            int src = __ffs(mask) - 1;
            mask &= mask - 1;
            const int k = src * 16 + c;
            const float4* er = (const float4*)(emb + (size_t)k * DIM) + l * 2;
            float4 e0 = er[0], e1 = er[1];
            float part = 0.f;
            part = fmaf(e0.x, xv[0], part);  part = fmaf(e0.y, xv[1], part);
            part = fmaf(e0.z, xv[2], part);  part = fmaf(e0.w, xv[3], part);
            part = fmaf(e1.x, xv[4], part);  part = fmaf(e1.y, xv[5], part);
            part = fmaf(e1.z, xv[6], part);  part = fmaf(e1.w, xv[7], part);
            #pragma unroll
            for (int m = 16; m >= 1; m >>= 1)
                part += __shfl_xor_sync(0xFFFFFFFFu, part, m);
            float dist = __fadd_rn(__fadd_rn(znv, d_enorm[k]),
                                   __fmul_rn(-2.f, part));         // validated rn
            unsigned u = __float_as_uint(dist);
            u = (u & 0x80000000u) ? ~u : (u | 0x80000000u);
            unsigned long long key = ((unsigned long long)u << 32) | (unsigned)k;
            if (key < best) best = key;
        }
    }
    if (l == 0) d_idx[p] = (int)(best & 0xFFFFFFFFull);
}

// ---------------- output: gather + validated rounding ----------------
__global__ __launch_bounds__(256) void vq_out(const float* __restrict__ x,
                                              const float* __restrict__ emb,
                                              float* __restrict__ out) {
    const int t   = threadIdx.x;
    const int pos = t & 127, dh = t >> 7;
    const int p   = blockIdx.x * TM + pos;
    const int b   = p >> 10;
    const int pbi = p & 1023;
    const int kq  = d_idx[p];
    const float* er = emb + (size_t)kq * DIM;
    const size_t gb = (size_t)b * DIM * HWSZ + pbi;
    #pragma unroll 4
    for (int d = dh * 128; d < dh * 128 + 128; ++d) {
        float v = __ldg(&er[d]);
        size_t off = gb + (size_t)d * HWSZ;
        float z = __ldg(&x[off]);
        out[off]           = __fadd_rn(z, __fadd_rn(v, -z));
        out[off + SEC]     = z;
        out[off + 2 * SEC] = v;
    }
}

extern "C" void kernel_launch(void* const* d_in, const int* in_sizes, int n_in,
                              void* d_out, int out_size) {
    const float* x   = (const float*)d_in[0];
    const float* emb = (const float*)d_in[1];
    float* out = (float*)d_out;
    (void)in_sizes; (void)n_in; (void)out_size;

    static int smem_set = 0;
    const int dyn = 2 * 128 * APITCH + 128 * SPITCH;   // A + B + score tile
    if (!smem_set) {
        cudaFuncSetAttribute(vq_main, cudaFuncAttributeMaxDynamicSharedMemorySize, dyn);
        smem_set = 1;
    }

    prep<<<272, 256>>>(x, emb);
    vq_main<<<NPOS / TM, 256, dyn>>>();
    fixup<<<NPOS / 8, 256>>>(x, emb);
    vq_out<<<NPOS / TM, 256>>>(x, emb, out);
}

// round 8
// speedup vs baseline: 3.3132x; 1.1937x over previous
#include <cuda_runtime.h>
#include <cuda_bf16.h>
#include <cuda_fp16.h>
#include <stdint.h>

// VQ-VAE quantization. R8: single fused kernel: HMMA bf16 scores (validated
// R6/R7) kept entirely in smem, in-CTA exact arbitration of near-ties
// (validated R7 arithmetic), smem-staged gather epilogue. Deletes the 64 MB
// score scratch and two launches.

#define BATCH 64
#define DIM   256
#define KCB   512
#define HWSZ  1024
#define NPOS  65536
#define TM    128
#define SEC   ((size_t)BATCH * DIM * HWSZ)
#define APITCH 528               // A/B smem row pitch (bytes), validated
#define SPITCH 1040              // score row pitch (bytes): 512 halves + pad
#define EPITCH 257               // e-stage row pitch (floats)
#define SCSZ   (128 * SPITCH)    // 133120 B; also holds A tile / e-stage
#define FLAG_M 1e-3f             // validated R6/R7
#define CAND_M 1.6e-3f           // validated R7 (incl. fp16 storage slack)

__device__ float d_enorm[KCB];
__device__ float d_zn[NPOS];
__device__ __nv_bfloat16 d_ebf[KCB * DIM];
__device__ __nv_bfloat16 d_xbf[(size_t)NPOS * DIM];

__device__ __forceinline__ uint32_t smem_u32(const void* p) {
    uint32_t a;
    asm("{ .reg .u64 t; cvta.to.shared.u64 t, %1; cvt.u32.u64 %0, t; }"
        : "=r"(a) : "l"(p));
    return a;
}
__device__ __forceinline__ void ldsm4(uint32_t r[4], uint32_t addr) {
    asm volatile("ldmatrix.sync.aligned.m8n8.x4.shared.b16 {%0,%1,%2,%3}, [%4];"
                 : "=r"(r[0]), "=r"(r[1]), "=r"(r[2]), "=r"(r[3]) : "r"(addr));
}
__device__ __forceinline__ void mma16816(float c[4], const uint32_t a[4],
                                         uint32_t b0, uint32_t b1) {
    asm volatile("mma.sync.aligned.m16n8k16.row.col.f32.bf16.bf16.f32 "
                 "{%0,%1,%2,%3}, {%4,%5,%6,%7}, {%8,%9}, {%0,%1,%2,%3};"
                 : "+f"(c[0]), "+f"(c[1]), "+f"(c[2]), "+f"(c[3])
                 : "r"(a[0]), "r"(a[1]), "r"(a[2]), "r"(a[3]), "r"(b0), "r"(b1));
}

// ---------------- prep (validated R7): x transpose+bf16+znorm, emb bf16+norm --
__global__ __launch_bounds__(256) void prep(const float* __restrict__ x,
                                            const float* __restrict__ emb) {
    if (blockIdx.x >= 256) {
        const int t = threadIdx.x;
        if (t < 32) {
            const int k = (blockIdx.x - 256) * 32 + t;
            const float4* e4 = (const float4*)(emb + (size_t)k * DIM);
            uint32_t* eb = ((uint32_t*)d_ebf) + (size_t)k * (DIM / 2);
            float acc = 0.f;
            #pragma unroll 4
            for (int j = 0; j < DIM / 4; ++j) {
                float4 v = e4[j];
                acc = __fadd_rn(acc, __fmul_rn(v.x, v.x));
                acc = __fadd_rn(acc, __fmul_rn(v.y, v.y));
                acc = __fadd_rn(acc, __fmul_rn(v.z, v.z));
                acc = __fadd_rn(acc, __fmul_rn(v.w, v.w));
                eb[2 * j] = (uint32_t)__bfloat16_as_ushort(__float2bfloat16(v.x)) |
                            ((uint32_t)__bfloat16_as_ushort(__float2bfloat16(v.y)) << 16);
                eb[2 * j + 1] = (uint32_t)__bfloat16_as_ushort(__float2bfloat16(v.z)) |
                                ((uint32_t)__bfloat16_as_ushort(__float2bfloat16(v.w)) << 16);
            }
            d_enorm[k] = acc;
        }
        return;
    }
    __shared__ float st[32][257];
    const int t  = threadIdx.x;
    const int p0 = blockIdx.x * 256;
    const int b  = p0 >> 10;
    const int pb = p0 & 1023;
    float acc = 0.f;
    for (int ch = 0; ch < 8; ++ch) {
        #pragma unroll 4
        for (int i = 0; i < 32; ++i) {
            int d = ch * 32 + i;
            st[i][t] = x[(size_t)b * DIM * HWSZ + (size_t)d * HWSZ + pb + t];
        }
        __syncthreads();
        uint32_t pk[16];
        #pragma unroll
        for (int j = 0; j < 16; ++j) {
            float v0 = st[2 * j][t], v1 = st[2 * j + 1][t];
            acc = __fadd_rn(acc, __fmul_rn(v0, v0));   // validated chain order
            acc = __fadd_rn(acc, __fmul_rn(v1, v1));
            pk[j] = (uint32_t)__bfloat16_as_ushort(__float2bfloat16(v0)) |
                    ((uint32_t)__bfloat16_as_ushort(__float2bfloat16(v1)) << 16);
        }
        uint4* dst = (uint4*)(d_xbf + (size_t)(p0 + t) * DIM + ch * 32);
        #pragma unroll
        for (int q = 0; q < 4; ++q) dst[q] = ((uint4*)pk)[q];
        __syncthreads();
    }
    d_zn[p0 + t] = acc;
}

// ---------------- fused main ----------------
__global__ __launch_bounds__(512, 1) void vq_fused(const float* __restrict__ x,
                                                   const float* __restrict__ emb,
                                                   float* __restrict__ out) {
    extern __shared__ char dsm[];
    __shared__ float en_s[KCB];
    __shared__ float m1s[TM][2], m2s[TM][2];
    __shared__ int ks_[TM][2];
    __shared__ int idx_s[TM];
    __shared__ int flist[TM];
    __shared__ int nflag;

    const int t   = threadIdx.x;
    const int wid = t >> 5;
    const int l   = t & 31;
    const int p0  = blockIdx.x * TM;
    const int b   = p0 >> 10;
    const int pb0 = p0 & 1023;

    char* Bp = dsm;                      // B tile, persistent
    char* SC = dsm + 128 * APITCH;       // scores; overlaps A staging + e-stage
    char* Ap = SC;
    const uint32_t Baddr = smem_u32(Bp);
    const uint32_t Aaddr = smem_u32(Ap);

    en_s[t] = d_enorm[t];
    if (t == 0) nflag = 0;

    {   // stage A tile (128 pos x 256 bf16)
        const uint4* src = (const uint4*)d_xbf;
        #pragma unroll
        for (int it = 0; it < 8; ++it) {
            int i = t + it * 512, row = i >> 5, seg = i & 31;
            *(uint4*)(Ap + row * APITCH + seg * 16) = src[(size_t)(p0 + row) * 32 + seg];
        }
    }
    __syncthreads();

    const int m0 = (wid & 7) * 16;       // warp's position rows
    const int nb = (wid >> 3) * 64;      // warp-group's code half within chunk
    uint32_t af[16][4];
    {
        uint32_t base = Aaddr + (uint32_t)(m0 + (l & 15)) * APITCH + (uint32_t)(l >> 4) * 16;
        #pragma unroll
        for (int ks = 0; ks < 16; ++ks) ldsm4(af[ks], base + ks * 32);
    }

    float min1a = 1e30f, min2a = 1e30f, min1b = 1e30f, min2b = 1e30f;
    int kma = 0, kmb = 0;
    const int row0 = m0 + (l >> 2);

    for (int nc = 0; nc < 4; ++nc) {
        __syncthreads();
        {   // stage B chunk (128 codes x 256 bf16)
            const uint4* src = (const uint4*)d_ebf;
            #pragma unroll
            for (int it = 0; it < 8; ++it) {
                int i = t + it * 512, row = i >> 5, seg = i & 31;
                *(uint4*)(Bp + row * APITCH + seg * 16) =
                    src[(size_t)(nc * 128 + row) * 32 + seg];
            }
        }
        __syncthreads();

        const uint32_t bbase = Baddr + (uint32_t)(nb + (l & 7)) * APITCH + (uint32_t)(l >> 3) * 16;
        for (int nt = 0; nt < 8; ++nt) {
            float c[4] = {0.f, 0.f, 0.f, 0.f};
            const uint32_t baddr = bbase + (uint32_t)nt * 8 * APITCH;
            #pragma unroll
            for (int ksp = 0; ksp < 8; ++ksp) {
                uint32_t br[4];
                ldsm4(br, baddr + ksp * 64);
                mma16816(c, af[2 * ksp],     br[0], br[1]);
                mma16816(c, af[2 * ksp + 1], br[2], br[3]);
            }
            const int kb = nc * 128 + nb + nt * 8 + ((l & 3) << 1);
            const float en0 = en_s[kb], en1 = en_s[kb + 1];
            float s0 = fmaf(-2.f, c[0], en0), s1 = fmaf(-2.f, c[1], en1);
            float s2 = fmaf(-2.f, c[2], en0), s3 = fmaf(-2.f, c[3], en1);
            *(__half2*)(SC + row0 * SPITCH + kb * 2)       = __floats2half2_rn(s0, s1);
            *(__half2*)(SC + (row0 + 8) * SPITCH + kb * 2) = __floats2half2_rn(s2, s3);
            if (s0 < min1a) { min2a = min1a; min1a = s0; kma = kb; }
            else if (s0 < min2a) min2a = s0;
            if (s1 < min1a) { min2a = min1a; min1a = s1; kma = kb + 1; }
            else if (s1 < min2a) min2a = s1;
            if (s2 < min1b) { min2b = min1b; min1b = s2; kmb = kb; }
            else if (s2 < min2b) min2b = s2;
            if (s3 < min1b) { min2b = min1b; min1b = s3; kmb = kb + 1; }
            else if (s3 < min2b) min2b = s3;
        }
    }

    // quad merge within warp (validated)
    #pragma unroll
    for (int msk = 1; msk <= 2; msk <<= 1) {
        float o1 = __shfl_xor_sync(0xFFFFFFFFu, min1a, msk);
        float o2 = __shfl_xor_sync(0xFFFFFFFFu, min2a, msk);
        int   ok = __shfl_xor_sync(0xFFFFFFFFu, kma,  msk);
        float hi = fmaxf(min1a, o1);
        if (o1 < min1a) { min1a = o1; kma = ok; }
        min2a = fminf(fminf(min2a, o2), hi);
        o1 = __shfl_xor_sync(0xFFFFFFFFu, min1b, msk);
        o2 = __shfl_xor_sync(0xFFFFFFFFu, min2b, msk);
        ok = __shfl_xor_sync(0xFFFFFFFFu, kmb,  msk);
        hi = fmaxf(min1b, o1);
        if (o1 < min1b) { min1b = o1; kmb = ok; }
        min2b = fminf(fminf(min2b, o2), hi);
    }
    const int wg = wid >> 3;
    if ((l & 3) == 0) {
        const int pa = m0 + (l >> 2);
        m1s[pa][wg] = min1a;  m2s[pa][wg] = min2a;  ks_[pa][wg] = kma;
        m1s[pa + 8][wg] = min1b;  m2s[pa + 8][wg] = min2b;  ks_[pa + 8][wg] = kmb;
    }
    __syncthreads();

    // merge the two warp-groups; flag near-ties
    if (t < TM) {
        float a1 = m1s[t][0], b1 = m1s[t][1];
        float lo = fminf(a1, b1), hi = fmaxf(a1, b1);
        int kf = (b1 < a1) ? ks_[t][1] : ks_[t][0];
        float m2 = fminf(fminf(m2s[t][0], m2s[t][1]), hi);
        idx_s[t] = kf;
        if (m2 - lo <= FLAG_M) { int sl = atomicAdd(&nflag, 1); flist[sl] = t; }
    }
    __syncthreads();

    // in-CTA exact arbitration (validated R7 arithmetic), warp per flagged pos
    const int nf = nflag;
    for (int i = wid; i < nf; i += 16) {
        const int pl = flist[i];
        const int p  = p0 + pl;
        const int pb = pb0 + pl;

        const uint4* rowq = (const uint4*)(SC + pl * SPITCH);
        __half2 hh[8];
        *(uint4*)&hh[0] = rowq[l * 2];
        *(uint4*)&hh[4] = rowq[l * 2 + 1];
        float s[16];
        #pragma unroll
        for (int j = 0; j < 8; ++j) {
            float2 f = __half22float2(hh[j]);
            s[2 * j] = f.x;  s[2 * j + 1] = f.y;
        }
        float smin = s[0];
        #pragma unroll
        for (int j = 1; j < 16; ++j) smin = fminf(smin, s[j]);
        #pragma unroll
        for (int m = 16; m >= 1; m >>= 1)
            smin = fminf(smin, __shfl_xor_sync(0xFFFFFFFFu, smin, m));
        const float lim = smin + CAND_M;

        const float* xc = x + (size_t)b * DIM * HWSZ + pb;
        float xv[8];
        #pragma unroll
        for (int j = 0; j < 8; ++j)
            xv[j] = __ldg(&xc[(size_t)(l * 8 + j) * HWSZ]);
        const float znv = d_zn[p];

        unsigned long long best = ~0ull;
        for (int c = 0; c < 16; ++c) {
            unsigned mask = __ballot_sync(0xFFFFFFFFu, s[c] <= lim);
            while (mask) {
                int src = __ffs(mask) - 1;
                mask &= mask - 1;
                const int k = src * 16 + c;
                const float4* er = (const float4*)(emb + (size_t)k * DIM) + l * 2;
                float4 e0 = er[0], e1 = er[1];
                float part = 0.f;
                part = fmaf(e0.x, xv[0], part);  part = fmaf(e0.y, xv[1], part);
                part = fmaf(e0.z, xv[2], part);  part = fmaf(e0.w, xv[3], part);
                part = fmaf(e1.x, xv[4], part);  part = fmaf(e1.y, xv[5], part);
                part = fmaf(e1.z, xv[6], part);  part = fmaf(e1.w, xv[7], part);
                #pragma unroll
                for (int m = 16; m >= 1; m >>= 1)
                    part += __shfl_xor_sync(0xFFFFFFFFu, part, m);
                float dist = __fadd_rn(__fadd_rn(znv, en_s[k]),
                                       __fmul_rn(-2.f, part));         // validated rn
                unsigned u = __float_as_uint(dist);
                u = (u & 0x80000000u) ? ~u : (u | 0x80000000u);
                unsigned long long key = ((unsigned long long)u << 32) | (unsigned)k;
                if (key < best) best = key;
            }
        }
        if (l == 0) idx_s[pl] = (int)(best & 0xFFFFFFFFull);
    }
    __syncthreads();

    // stage gathered e-rows into smem (coalesced, conflict-free pad)
    float* es = (float*)SC;
    for (int r = wid; r < TM; r += 16) {
        const float* er = emb + (size_t)idx_s[r] * DIM;
        #pragma unroll
        for (int j = 0; j < 8; ++j)
            es[r * EPITCH + j * 32 + l] = __ldg(&er[j * 32 + l]);
    }
    __syncthreads();

    // streaming epilogue: coalesced 128B rows only
    {
        const int pos = t & 127, dh = t >> 7;     // dh 0..3, 64 d each
        const size_t gb = (size_t)b * DIM * HWSZ + pb0 + pos;
        const float* esr = es + pos * EPITCH;
        #pragma unroll 4
        for (int d = dh * 64; d < dh * 64 + 64; ++d) {
            float v = esr[d];
            size_t off = gb + (size_t)d * HWSZ;
            float z = __ldg(&x[off]);
            out[off]           = __fadd_rn(z, __fadd_rn(v, -z));   // validated rounding
            out[off + SEC]     = z;
            out[off + 2 * SEC] = v;
        }
    }
}

extern "C" void kernel_launch(void* const* d_in, const int* in_sizes, int n_in,
                              void* d_out, int out_size) {
    const float* x   = (const float*)d_in[0];
    const float* emb = (const float*)d_in[1];
    float* out = (float*)d_out;
    (void)in_sizes; (void)n_in; (void)out_size;

    static int smem_set = 0;
    const int dyn = 128 * APITCH + SCSZ;   // B + score/A/e-stage region = 200704
    if (!smem_set) {
        cudaFuncSetAttribute(vq_fused, cudaFuncAttributeMaxDynamicSharedMemorySize, dyn);
        smem_set = 1;
    }

    prep<<<272, 256>>>(x, emb);
    vq_fused<<<NPOS / TM, 512, dyn>>>(x, emb, out);
}

// round 9
// speedup vs baseline: 4.0027x; 1.2081x over previous
#include <cuda_runtime.h>
#include <cuda_bf16.h>
#include <cuda_fp16.h>
#include <stdint.h>

// VQ-VAE quantization. R9: fully fused kernel. In-kernel A-tile build
// (fp32 x -> bf16 transpose via smem; conversion identical to validated prep)
// + in-kernel sequential-chain znorm (bit-identical arithmetic, relocated) +
// HMMA scores in smem + exact arbitration + staged-gather epilogue
// (all validated R6-R8, rel_err==0.0). Only a tiny emb prep kernel remains.

#define BATCH 64
#define DIM   256
#define KCB   512
#define HWSZ  1024
#define NPOS  65536
#define TM    128
#define SEC   ((size_t)BATCH * DIM * HWSZ)
#define APITCH 528               // A/B smem row pitch (bytes), validated
#define SPITCH 1040              // score row pitch (bytes): 512 halves + pad
#define EPITCH 257               // e-stage row pitch (floats)
#define SCSZ   (128 * SPITCH)
#define STP    133               // fp32 staging pitch (floats), conflict-free
#define FLAG_M 1e-3f             // validated
#define CAND_M 1.6e-3f           // validated

__device__ float d_enorm[KCB];
__device__ __nv_bfloat16 d_ebf[KCB * DIM];

__device__ __forceinline__ uint32_t smem_u32(const void* p) {
    uint32_t a;
    asm("{ .reg .u64 t; cvta.to.shared.u64 t, %1; cvt.u32.u64 %0, t; }"
        : "=r"(a) : "l"(p));
    return a;
}
__device__ __forceinline__ void ldsm4(uint32_t r[4], uint32_t addr) {
    asm volatile("ldmatrix.sync.aligned.m8n8.x4.shared.b16 {%0,%1,%2,%3}, [%4];"
                 : "=r"(r[0]), "=r"(r[1]), "=r"(r[2]), "=r"(r[3]) : "r"(addr));
}
__device__ __forceinline__ void mma16816(float c[4], const uint32_t a[4],
                                         uint32_t b0, uint32_t b1) {
    asm volatile("mma.sync.aligned.m16n8k16.row.col.f32.bf16.bf16.f32 "
                 "{%0,%1,%2,%3}, {%4,%5,%6,%7}, {%8,%9}, {%0,%1,%2,%3};"
                 : "+f"(c[0]), "+f"(c[1]), "+f"(c[2]), "+f"(c[3])
                 : "r"(a[0]), "r"(a[1]), "r"(a[2]), "r"(a[3]), "r"(b0), "r"(b1));
}

// ---------------- emb prep (validated R7 arithmetic) ----------------
__global__ void prep_e(const float* __restrict__ emb) {
    const int k = blockIdx.x * 32 + threadIdx.x;
    if (k >= KCB) return;
    const float4* e4 = (const float4*)(emb + (size_t)k * DIM);
    uint32_t* eb = ((uint32_t*)d_ebf) + (size_t)k * (DIM / 2);
    float acc = 0.f;
    #pragma unroll 4
    for (int j = 0; j < DIM / 4; ++j) {
        float4 v = e4[j];
        acc = __fadd_rn(acc, __fmul_rn(v.x, v.x));
        acc = __fadd_rn(acc, __fmul_rn(v.y, v.y));
        acc = __fadd_rn(acc, __fmul_rn(v.z, v.z));
        acc = __fadd_rn(acc, __fmul_rn(v.w, v.w));
        eb[2 * j] = (uint32_t)__bfloat16_as_ushort(__float2bfloat16(v.x)) |
                    ((uint32_t)__bfloat16_as_ushort(__float2bfloat16(v.y)) << 16);
        eb[2 * j + 1] = (uint32_t)__bfloat16_as_ushort(__float2bfloat16(v.z)) |
                        ((uint32_t)__bfloat16_as_ushort(__float2bfloat16(v.w)) << 16);
    }
    d_enorm[k] = acc;
}

// ---------------- fused main ----------------
__global__ __launch_bounds__(512, 1) void vq_fused(const float* __restrict__ x,
                                                   const float* __restrict__ emb,
                                                   float* __restrict__ out) {
    extern __shared__ char dsm[];
    __shared__ float en_s[KCB];
    __shared__ float zn_s[TM];
    __shared__ float m1s[TM][2], m2s[TM][2];
    __shared__ int ks_[TM][2];
    __shared__ int idx_s[TM];
    __shared__ int flist[TM];
    __shared__ int nflag;

    const int t   = threadIdx.x;
    const int wid = t >> 5;
    const int l   = t & 31;
    const int p0  = blockIdx.x * TM;
    const int b   = p0 >> 10;
    const int pb0 = p0 & 1023;

    char* Bp = dsm;                      // B tile; also fp32 staging + xcol scratch
    char* SC = dsm + 128 * APITCH;       // scores; overlaps A tile + e-stage
    char* Ap = SC;
    const uint32_t Baddr = smem_u32(Bp);
    const uint32_t Aaddr = smem_u32(Ap);

    en_s[t] = d_enorm[t];
    if (t == 0) nflag = 0;

    // ---- A-build: fp32 x -> bf16 A tile + sequential znorm chain ----
    {
        float* st = (float*)Bp;              // [32][STP] fp32 staging
        float zacc = 0.f;
        const float* gx = x + (size_t)b * DIM * HWSZ + pb0;
        for (int ch = 0; ch < 8; ++ch) {
            __syncthreads();
            #pragma unroll
            for (int it = 0; it < 8; ++it) {
                int i = t + it * 512, r = i >> 7, pos = i & 127;
                st[r * STP + pos] = gx[(size_t)(ch * 32 + r) * HWSZ + pos];
            }
            __syncthreads();
            if (t < TM) {                    // znorm: strictly sequential in d
                #pragma unroll 8
                for (int r = 0; r < 32; ++r) {
                    float v = st[r * STP + t];
                    zacc = __fadd_rn(zacc, __fmul_rn(v, v));
                }
            }
            {                                // pack bf16 into A[pos][d]
                const int pos = t >> 2, sub = t & 3;
                uint32_t pk[4];
                #pragma unroll
                for (int j = 0; j < 4; ++j) {
                    float v0 = st[(sub * 8 + 2 * j) * STP + pos];
                    float v1 = st[(sub * 8 + 2 * j + 1) * STP + pos];
                    pk[j] = (uint32_t)__bfloat16_as_ushort(__float2bfloat16(v0)) |
                            ((uint32_t)__bfloat16_as_ushort(__float2bfloat16(v1)) << 16);
                }
                *(uint4*)(Ap + pos * APITCH + ch * 64 + sub * 16) =
                    make_uint4(pk[0], pk[1], pk[2], pk[3]);
            }
        }
        if (t < TM) zn_s[t] = zacc;
    }
    __syncthreads();

    // ---- A fragments (validated layout) ----
    const int m0 = (wid & 7) * 16;
    const int nb = (wid >> 3) * 64;
    uint32_t af[16][4];
    {
        uint32_t base = Aaddr + (uint32_t)(m0 + (l & 15)) * APITCH + (uint32_t)(l >> 4) * 16;
        #pragma unroll
        for (int ks = 0; ks < 16; ++ks) ldsm4(af[ks], base + ks * 32);
    }

    float min1a = 1e30f, min2a = 1e30f, min1b = 1e30f, min2b = 1e30f;
    int kma = 0, kmb = 0;
    const int row0 = m0 + (l >> 2);

    for (int nc = 0; nc < 4; ++nc) {
        __syncthreads();
        {   // stage B chunk
            const uint4* src = (const uint4*)d_ebf;
            #pragma unroll
            for (int it = 0; it < 8; ++it) {
                int i = t + it * 512, row = i >> 5, seg = i & 31;
                *(uint4*)(Bp + row * APITCH + seg * 16) =
                    src[(size_t)(nc * 128 + row) * 32 + seg];
            }
        }
        __syncthreads();

        const uint32_t bbase = Baddr + (uint32_t)(nb + (l & 7)) * APITCH + (uint32_t)(l >> 3) * 16;
        for (int nt = 0; nt < 8; ++nt) {
            float c[4] = {0.f, 0.f, 0.f, 0.f};
            const uint32_t baddr = bbase + (uint32_t)nt * 8 * APITCH;
            #pragma unroll
            for (int ksp = 0; ksp < 8; ++ksp) {
                uint32_t br[4];
                ldsm4(br, baddr + ksp * 64);
                mma16816(c, af[2 * ksp],     br[0], br[1]);
                mma16816(c, af[2 * ksp + 1], br[2], br[3]);
            }
            const int kb = nc * 128 + nb + nt * 8 + ((l & 3) << 1);
            const float en0 = en_s[kb], en1 = en_s[kb + 1];
            float s0 = fmaf(-2.f, c[0], en0), s1 = fmaf(-2.f, c[1], en1);
            float s2 = fmaf(-2.f, c[2], en0), s3 = fmaf(-2.f, c[3], en1);
            *(__half2*)(SC + row0 * SPITCH + kb * 2)       = __floats2half2_rn(s0, s1);
            *(__half2*)(SC + (row0 + 8) * SPITCH + kb * 2) = __floats2half2_rn(s2, s3);
            if (s0 < min1a) { min2a = min1a; min1a = s0; kma = kb; }
            else if (s0 < min2a) min2a = s0;
            if (s1 < min1a) { min2a = min1a; min1a = s1; kma = kb + 1; }
            else if (s1 < min2a) min2a = s1;
            if (s2 < min1b) { min2b = min1b; min1b = s2; kmb = kb; }
            else if (s2 < min2b) min2b = s2;
            if (s3 < min1b) { min2b = min1b; min1b = s3; kmb = kb + 1; }
            else if (s3 < min2b) min2b = s3;
        }
    }

    // quad merge within warp (validated)
    #pragma unroll
    for (int msk = 1; msk <= 2; msk <<= 1) {
        float o1 = __shfl_xor_sync(0xFFFFFFFFu, min1a, msk);
        float o2 = __shfl_xor_sync(0xFFFFFFFFu, min2a, msk);
        int   ok = __shfl_xor_sync(0xFFFFFFFFu, kma,  msk);
        float hi = fmaxf(min1a, o1);
        if (o1 < min1a) { min1a = o1; kma = ok; }
        min2a = fminf(fminf(min2a, o2), hi);
        o1 = __shfl_xor_sync(0xFFFFFFFFu, min1b, msk);
        o2 = __shfl_xor_sync(0xFFFFFFFFu, min2b, msk);
        ok = __shfl_xor_sync(0xFFFFFFFFu, kmb,  msk);
        hi = fmaxf(min1b, o1);
        if (o1 < min1b) { min1b = o1; kmb = ok; }
        min2b = fminf(fminf(min2b, o2), hi);
    }
    const int wg = wid >> 3;
    if ((l & 3) == 0) {
        const int pa = m0 + (l >> 2);
        m1s[pa][wg] = min1a;  m2s[pa][wg] = min2a;  ks_[pa][wg] = kma;
        m1s[pa + 8][wg] = min1b;  m2s[pa + 8][wg] = min2b;  ks_[pa + 8][wg] = kmb;
    }
    __syncthreads();

    if (t < TM) {
        float a1 = m1s[t][0], b1 = m1s[t][1];
        float lo = fminf(a1, b1), hi = fmaxf(a1, b1);
        int kf = (b1 < a1) ? ks_[t][1] : ks_[t][0];
        float m2 = fminf(fminf(m2s[t][0], m2s[t][1]), hi);
        idx_s[t] = kf;
        if (m2 - lo <= FLAG_M) { int sl = atomicAdd(&nflag, 1); flist[sl] = t; }
    }
    __syncthreads();

    // ---- exact arbitration (validated R7/R8 arithmetic; znv from zn_s) ----
    const int nf = nflag;
    for (int i = wid; i < nf; i += 16) {
        const int pl = flist[i];
        const int pb = pb0 + pl;

        const uint4* rowq = (const uint4*)(SC + pl * SPITCH);
        __half2 hh[8];
        *(uint4*)&hh[0] = rowq[l * 2];
        *(uint4*)&hh[4] = rowq[l * 2 + 1];
        float s[16];
        #pragma unroll
        for (int j = 0; j < 8; ++j) {
            float2 f = __half22float2(hh[j]);
            s[2 * j] = f.x;  s[2 * j + 1] = f.y;
        }
        float smin = s[0];
        #pragma unroll
        for (int j = 1; j < 16; ++j) smin = fminf(smin, s[j]);
        #pragma unroll
        for (int m = 16; m >= 1; m >>= 1)
            smin = fminf(smin, __shfl_xor_sync(0xFFFFFFFFu, smin, m));
        const float lim = smin + CAND_M;

        const float* xc = x + (size_t)b * DIM * HWSZ + pb;
        float xv[8];
        #pragma unroll
        for (int j = 0; j < 8; ++j)
            xv[j] = __ldg(&xc[(size_t)(l * 8 + j) * HWSZ]);
        const float znv = zn_s[pl];

        unsigned long long best = ~0ull;
        for (int c = 0; c < 16; ++c) {
            unsigned mask = __ballot_sync(0xFFFFFFFFu, s[c] <= lim);
            while (mask) {
                int src = __ffs(mask) - 1;
                mask &= mask - 1;
                const int k = src * 16 + c;
                const float4* er = (const float4*)(emb + (size_t)k * DIM) + l * 2;
                float4 e0 = er[0], e1 = er[1];
                float part = 0.f;
                part = fmaf(e0.x, xv[0], part);  part = fmaf(e0.y, xv[1], part);
                part = fmaf(e0.z, xv[2], part);  part = fmaf(e0.w, xv[3], part);
                part = fmaf(e1.x, xv[4], part);  part = fmaf(e1.y, xv[5], part);
                part = fmaf(e1.z, xv[6], part);  part = fmaf(e1.w, xv[7], part);
                #pragma unroll
                for (int m = 16; m >= 1; m >>= 1)
                    part += __shfl_xor_sync(0xFFFFFFFFu, part, m);
                float dist = __fadd_rn(__fadd_rn(znv, en_s[k]),
                                       __fmul_rn(-2.f, part));
                unsigned u = __float_as_uint(dist);
                u = (u & 0x80000000u) ? ~u : (u | 0x80000000u);
                unsigned long long key = ((unsigned long long)u << 32) | (unsigned)k;
                if (key < best) best = key;
            }
        }
        if (l == 0) idx_s[pl] = (int)(best & 0xFFFFFFFFull);
    }
    __syncthreads();

    // ---- gather e-rows to smem + streaming epilogue (validated) ----
    float* es = (float*)SC;
    for (int r = wid; r < TM; r += 16) {
        const float* er = emb + (size_t)idx_s[r] * DIM;
        #pragma unroll
        for (int j = 0; j < 8; ++j)
            es[r * EPITCH + j * 32 + l] = __ldg(&er[j * 32 + l]);
    }
    __syncthreads();

    {
        const int pos = t & 127, dh = t >> 7;
        const size_t gb = (size_t)b * DIM * HWSZ + pb0 + pos;
        const float* esr = es + pos * EPITCH;
        #pragma unroll 4
        for (int d = dh * 64; d < dh * 64 + 64; ++d) {
            float v = esr[d];
            size_t off = gb + (size_t)d * HWSZ;
            float z = __ldg(&x[off]);
            out[off]           = __fadd_rn(z, __fadd_rn(v, -z));
            out[off + SEC]     = z;
            out[off + 2 * SEC] = v;
        }
    }
}

extern "C" void kernel_launch(void* const* d_in, const int* in_sizes, int n_in,
                              void* d_out, int out_size) {
    const float* x   = (const float*)d_in[0];
    const float* emb = (const float*)d_in[1];
    float* out = (float*)d_out;
    (void)in_sizes; (void)n_in; (void)out_size;

    static int smem_set = 0;
    const int dyn = 128 * APITCH + SCSZ;   // 200704 B
    if (!smem_set) {
        cudaFuncSetAttribute(vq_fused, cudaFuncAttributeMaxDynamicSharedMemorySize, dyn);
        smem_set = 1;
    }

    prep_e<<<16, 32>>>(emb);
    vq_fused<<<NPOS / TM, 512, dyn>>>(x, emb, out);
}

// round 10
// speedup vs baseline: 4.0629x; 1.0150x over previous
#include <cuda_runtime.h>
#include <cuda_bf16.h>
#include <cuda_fp16.h>
#include <stdint.h>

// VQ-VAE quantization. R10: fused kernel at TM=64/256 threads so two CTAs fit
// per SM (smem 100K): MMA-latency and DRAM phases overlap across resident
// CTAs. All score/argmin/fixup/output arithmetic is bit-identical to the
// validated R6-R9 pipeline (rel_err==0.0); only tiling indices changed.

#define BATCH 64
#define DIM   256
#define KCB   512
#define HWSZ  1024
#define NPOS  65536
#define TM    64
#define SEC   ((size_t)BATCH * DIM * HWSZ)
#define APITCH 528               // A/B smem row pitch (bytes), validated
#define SPITCH 1040              // score row pitch (bytes): 512 halves + pad
#define EPITCH 257               // e-stage row pitch (floats)
#define STP    133               // fp32 staging pitch (floats)
#define FLAG_M 1e-3f             // validated
#define CAND_M 1.6e-3f           // validated

__device__ float d_enorm[KCB];
__device__ __nv_bfloat16 d_ebf[KCB * DIM];

__device__ __forceinline__ uint32_t smem_u32(const void* p) {
    uint32_t a;
    asm("{ .reg .u64 t; cvta.to.shared.u64 t, %1; cvt.u32.u64 %0, t; }"
        : "=r"(a) : "l"(p));
    return a;
}
__device__ __forceinline__ void ldsm4(uint32_t r[4], uint32_t addr) {
    asm volatile("ldmatrix.sync.aligned.m8n8.x4.shared.b16 {%0,%1,%2,%3}, [%4];"
                 : "=r"(r[0]), "=r"(r[1]), "=r"(r[2]), "=r"(r[3]) : "r"(addr));
}
__device__ __forceinline__ void mma16816(float c[4], const uint32_t a[4],
                                         uint32_t b0, uint32_t b1) {
    asm volatile("mma.sync.aligned.m16n8k16.row.col.f32.bf16.bf16.f32 "
                 "{%0,%1,%2,%3}, {%4,%5,%6,%7}, {%8,%9}, {%0,%1,%2,%3};"
                 : "+f"(c[0]), "+f"(c[1]), "+f"(c[2]), "+f"(c[3])
                 : "r"(a[0]), "r"(a[1]), "r"(a[2]), "r"(a[3]), "r"(b0), "r"(b1));
}

// ---------------- emb prep (validated) ----------------
__global__ void prep_e(const float* __restrict__ emb) {
    const int k = blockIdx.x * 32 + threadIdx.x;
    if (k >= KCB) return;
    const float4* e4 = (const float4*)(emb + (size_t)k * DIM);
    uint32_t* eb = ((uint32_t*)d_ebf) + (size_t)k * (DIM / 2);
    float acc = 0.f;
    #pragma unroll 4
    for (int j = 0; j < DIM / 4; ++j) {
        float4 v = e4[j];
        acc = __fadd_rn(acc, __fmul_rn(v.x, v.x));
        acc = __fadd_rn(acc, __fmul_rn(v.y, v.y));
        acc = __fadd_rn(acc, __fmul_rn(v.z, v.z));
        acc = __fadd_rn(acc, __fmul_rn(v.w, v.w));
        eb[2 * j] = (uint32_t)__bfloat16_as_ushort(__float2bfloat16(v.x)) |
                    ((uint32_t)__bfloat16_as_ushort(__float2bfloat16(v.y)) << 16);
        eb[2 * j + 1] = (uint32_t)__bfloat16_as_ushort(__float2bfloat16(v.z)) |
                        ((uint32_t)__bfloat16_as_ushort(__float2bfloat16(v.w)) << 16);
    }
    d_enorm[k] = acc;
}

// ---------------- fused main ----------------
__global__ __launch_bounds__(256, 2) void vq_fused(const float* __restrict__ x,
                                                   const float* __restrict__ emb,
                                                   float* __restrict__ out) {
    extern __shared__ char dsm[];
    __shared__ float en_s[KCB];
    __shared__ float zn_s[TM];
    __shared__ float m1s[TM][2], m2s[TM][2];
    __shared__ int ks_[TM][2];
    __shared__ int idx_s[TM];
    __shared__ int flist[TM];
    __shared__ int nflag;

    const int t   = threadIdx.x;
    const int wid = t >> 5;
    const int l   = t & 31;
    const int p0  = blockIdx.x * TM;
    const int b   = p0 >> 10;
    const int pb0 = p0 & 1023;

    char* Bp = dsm;                      // B chunk (64 codes); also fp32 staging
    char* SC = dsm + TM * APITCH;        // scores; overlaps A tile + e-stage
    char* Ap = SC;
    const uint32_t Baddr = smem_u32(Bp);
    const uint32_t Aaddr = smem_u32(Ap);

    en_s[t] = d_enorm[t];
    en_s[t + 256] = d_enorm[t + 256];
    if (t == 0) nflag = 0;

    // ---- A-build: fp32 x -> bf16 A tile (64 x 256) + sequential znorm ----
    {
        float* st = (float*)Bp;              // [32][STP] fp32 staging (17KB)
        float zacc = 0.f;
        const float* gx = x + (size_t)b * DIM * HWSZ + pb0;
        for (int ch = 0; ch < 8; ++ch) {
            __syncthreads();
            #pragma unroll
            for (int it = 0; it < 8; ++it) {
                int i = t + it * 256, r = i >> 6, pos = i & 63;
                st[r * STP + pos] = gx[(size_t)(ch * 32 + r) * HWSZ + pos];
            }
            __syncthreads();
            if (t < TM) {                    // znorm: strictly sequential in d
                #pragma unroll 8
                for (int r = 0; r < 32; ++r) {
                    float v = st[r * STP + t];
                    zacc = __fadd_rn(zacc, __fmul_rn(v, v));
                }
            }
            {                                // pack bf16 into A[pos][d]
                const int pos = t >> 2, sub = t & 3;
                uint32_t pk[4];
                #pragma unroll
                for (int j = 0; j < 4; ++j) {
                    float v0 = st[(sub * 8 + 2 * j) * STP + pos];
                    float v1 = st[(sub * 8 + 2 * j + 1) * STP + pos];
                    pk[j] = (uint32_t)__bfloat16_as_ushort(__float2bfloat16(v0)) |
                            ((uint32_t)__bfloat16_as_ushort(__float2bfloat16(v1)) << 16);
                }
                *(uint4*)(Ap + pos * APITCH + ch * 64 + sub * 16) =
                    make_uint4(pk[0], pk[1], pk[2], pk[3]);
            }
        }
        if (t < TM) zn_s[t] = zacc;
    }
    __syncthreads();

    // ---- A fragments (validated layout): 4 M-groups x 2 N-groups ----
    const int m0 = (wid & 3) * 16;       // warp's 16 position rows
    const int nb = (wid >> 2) * 32;      // warp's code half within 64-chunk
    uint32_t af[16][4];
    {
        uint32_t base = Aaddr + (uint32_t)(m0 + (l & 15)) * APITCH + (uint32_t)(l >> 4) * 16;
        #pragma unroll
        for (int ks = 0; ks < 16; ++ks) ldsm4(af[ks], base + ks * 32);
    }

    float min1a = 1e30f, min2a = 1e30f, min1b = 1e30f, min2b = 1e30f;
    int kma = 0, kmb = 0;
    const int row0 = m0 + (l >> 2);

    for (int nc = 0; nc < 8; ++nc) {       // 8 chunks of 64 codes
        __syncthreads();
        {   // stage B chunk (64 codes x 256 bf16)
            const uint4* src = (const uint4*)d_ebf;
            #pragma unroll
            for (int it = 0; it < 8; ++it) {
                int i = t + it * 256, row = i >> 5, seg = i & 31;
                *(uint4*)(Bp + row * APITCH + seg * 16) =
                    src[(size_t)(nc * 64 + row) * 32 + seg];
            }
        }
        __syncthreads();

        const uint32_t bbase = Baddr + (uint32_t)(nb + (l & 7)) * APITCH + (uint32_t)(l >> 3) * 16;
        for (int nt = 0; nt < 4; ++nt) {
            float c[4] = {0.f, 0.f, 0.f, 0.f};
            const uint32_t baddr = bbase + (uint32_t)nt * 8 * APITCH;
            #pragma unroll
            for (int ksp = 0; ksp < 8; ++ksp) {
                uint32_t br[4];
                ldsm4(br, baddr + ksp * 64);
                mma16816(c, af[2 * ksp],     br[0], br[1]);
                mma16816(c, af[2 * ksp + 1], br[2], br[3]);
            }
            const int kb = nc * 64 + nb + nt * 8 + ((l & 3) << 1);
            const float en0 = en_s[kb], en1 = en_s[kb + 1];
            float s0 = fmaf(-2.f, c[0], en0), s1 = fmaf(-2.f, c[1], en1);
            float s2 = fmaf(-2.f, c[2], en0), s3 = fmaf(-2.f, c[3], en1);
            *(__half2*)(SC + row0 * SPITCH + kb * 2)       = __floats2half2_rn(s0, s1);
            *(__half2*)(SC + (row0 + 8) * SPITCH + kb * 2) = __floats2half2_rn(s2, s3);
            if (s0 < min1a) { min2a = min1a; min1a = s0; kma = kb; }
            else if (s0 < min2a) min2a = s0;
            if (s1 < min1a) { min2a = min1a; min1a = s1; kma = kb + 1; }
            else if (s1 < min2a) min2a = s1;
            if (s2 < min1b) { min2b = min1b; min1b = s2; kmb = kb; }
            else if (s2 < min2b) min2b = s2;
            if (s3 < min1b) { min2b = min1b; min1b = s3; kmb = kb + 1; }
            else if (s3 < min2b) min2b = s3;
        }
    }

    // quad merge within warp (validated)
    #pragma unroll
    for (int msk = 1; msk <= 2; msk <<= 1) {
        float o1 = __shfl_xor_sync(0xFFFFFFFFu, min1a, msk);
        float o2 = __shfl_xor_sync(0xFFFFFFFFu, min2a, msk);
        int   ok = __shfl_xor_sync(0xFFFFFFFFu, kma,  msk);
        float hi = fmaxf(min1a, o1);
        if (o1 < min1a) { min1a = o1; kma = ok; }
        min2a = fminf(fminf(min2a, o2), hi);
        o1 = __shfl_xor_sync(0xFFFFFFFFu, min1b, msk);
        o2 = __shfl_xor_sync(0xFFFFFFFFu, min2b, msk);
        ok = __shfl_xor_sync(0xFFFFFFFFu, kmb,  msk);
        hi = fmaxf(min1b, o1);
        if (o1 < min1b) { min1b = o1; kmb = ok; }
        min2b = fminf(fminf(min2b, o2), hi);
    }
    const int wg = wid >> 2;
    if ((l & 3) == 0) {
        const int pa = m0 + (l >> 2);
        m1s[pa][wg] = min1a;  m2s[pa][wg] = min2a;  ks_[pa][wg] = kma;
        m1s[pa + 8][wg] = min1b;  m2s[pa + 8][wg] = min2b;  ks_[pa + 8][wg] = kmb;
    }
    __syncthreads();

    if (t < TM) {
        float a1 = m1s[t][0], b1 = m1s[t][1];
        float lo = fminf(a1, b1), hi = fmaxf(a1, b1);
        int kf = (b1 < a1) ? ks_[t][1] : ks_[t][0];
        float m2 = fminf(fminf(m2s[t][0], m2s[t][1]), hi);
        idx_s[t] = kf;
        if (m2 - lo <= FLAG_M) { int sl = atomicAdd(&nflag, 1); flist[sl] = t; }
    }
    __syncthreads();

    // ---- exact arbitration (validated arithmetic), warp per flagged pos ----
    const int nf = nflag;
    for (int i = wid; i < nf; i += 8) {
        const int pl = flist[i];
        const int pb = pb0 + pl;

        const uint4* rowq = (const uint4*)(SC + pl * SPITCH);
        __half2 hh[8];
        *(uint4*)&hh[0] = rowq[l * 2];
        *(uint4*)&hh[4] = rowq[l * 2 + 1];
        float s[16];
        #pragma unroll
        for (int j = 0; j < 8; ++j) {
            float2 f = __half22float2(hh[j]);
            s[2 * j] = f.x;  s[2 * j + 1] = f.y;
        }
        float smin = s[0];
        #pragma unroll
        for (int j = 1; j < 16; ++j) smin = fminf(smin, s[j]);
        #pragma unroll
        for (int m = 16; m >= 1; m >>= 1)
            smin = fminf(smin, __shfl_xor_sync(0xFFFFFFFFu, smin, m));
        const float lim = smin + CAND_M;

        const float* xc = x + (size_t)b * DIM * HWSZ + pb;
        float xv[8];
        #pragma unroll
        for (int j = 0; j < 8; ++j)
            xv[j] = __ldg(&xc[(size_t)(l * 8 + j) * HWSZ]);
        const float znv = zn_s[pl];

        unsigned long long best = ~0ull;
        for (int c = 0; c < 16; ++c) {
            unsigned mask = __ballot_sync(0xFFFFFFFFu, s[c] <= lim);
            while (mask) {
                int src = __ffs(mask) - 1;
                mask &= mask - 1;
                const int k = src * 16 + c;
                const float4* er = (const float4*)(emb + (size_t)k * DIM) + l * 2;
                float4 e0 = er[0], e1 = er[1];
                float part = 0.f;
                part = fmaf(e0.x, xv[0], part);  part = fmaf(e0.y, xv[1], part);
                part = fmaf(e0.z, xv[2], part);  part = fmaf(e0.w, xv[3], part);
                part = fmaf(e1.x, xv[4], part);  part = fmaf(e1.y, xv[5], part);
                part = fmaf(e1.z, xv[6], part);  part = fmaf(e1.w, xv[7], part);
                #pragma unroll
                for (int m = 16; m >= 1; m >>= 1)
                    part += __shfl_xor_sync(0xFFFFFFFFu, part, m);
                float dist = __fadd_rn(__fadd_rn(znv, en_s[k]),
                                       __fmul_rn(-2.f, part));
                unsigned u = __float_as_uint(dist);
                u = (u & 0x80000000u) ? ~u : (u | 0x80000000u);
                unsigned long long key = ((unsigned long long)u << 32) | (unsigned)k;
                if (key < best) best = key;
            }
        }
        if (l == 0) idx_s[pl] = (int)(best & 0xFFFFFFFFull);
    }
    __syncthreads();

    // ---- gather e-rows to smem + streaming epilogue (validated) ----
    float* es = (float*)SC;
    for (int r = wid; r < TM; r += 8) {
        const float* er = emb + (size_t)idx_s[r] * DIM;
        #pragma unroll
        for (int j = 0; j < 8; ++j)
            es[r * EPITCH + j * 32 + l] = __ldg(&er[j * 32 + l]);
    }
    __syncthreads();

    {
        const int pos = t & 63, dh = t >> 6;        // dh 0..3, 64 d each
        const size_t gb = (size_t)b * DIM * HWSZ + pb0 + pos;
        const float* esr = es + pos * EPITCH;
        #pragma unroll 4
        for (int d = dh * 64; d < dh * 64 + 64; ++d) {
            float v = esr[d];
            size_t off = gb + (size_t)d * HWSZ;
            float z = __ldg(&x[off]);
            out[off]           = __fadd_rn(z, __fadd_rn(v, -z));
            out[off + SEC]     = z;
            out[off + 2 * SEC] = v;
        }
    }
}

extern "C" void kernel_launch(void* const* d_in, const int* in_sizes, int n_in,
                              void* d_out, int out_size) {
    const float* x   = (const float*)d_in[0];
    const float* emb = (const float*)d_in[1];
    float* out = (float*)d_out;
    (void)in_sizes; (void)n_in; (void)out_size;

    static int smem_set = 0;
    const int dyn = TM * APITCH + TM * SPITCH;   // 33792 + 66560 = 100352 B
    if (!smem_set) {
        cudaFuncSetAttribute(vq_fused, cudaFuncAttributeMaxDynamicSharedMemorySize, dyn);
        smem_set = 1;
    }

    prep_e<<<16, 32>>>(emb);
    vq_fused<<<NPOS / TM, 256, dyn>>>(x, emb, out);
}